// round 15
// baseline (speedup 1.0000x reference)
#include <cuda_runtime.h>
#include <cuda_bf16.h>
#include <stdint.h>

#define HH 128
#define NB_ 2
#define NN 16384
#define KK 16
#define NPB 8
#define NTH 256
#define PDK 136                      // bf16 row stride (272B, 16B-aligned, conflict-free)
#define TILEB (128 * PDK * 2)        // 34816 bytes per tile

// smem byte offsets
#define S_AH 0
#define S_AL 34816
#define S_BH 69632
#define S_BL 104448
#define S_HI 139264                  // float[8][128]
#define S_SI 143360                  // float[8][128]
#define S_MI 147456                  // float[8][128]
#define S_N1 151552                  // float[8][128]
#define S_BE1 155648
#define S_WSQ 156160
#define S_BE2 156672
#define S_BC1 157184
#define S_WC2 157696
#define S_SQD 158208                 // float[128]
#define S_XD  158720                 // float[128*3]
#define S_XI  160256                 // float[8*4]
#define S_CWP 160384                 // float[128*2]
#define S_IDX 161408                 // int[128]
#define SMEM_TOTAL 161920

typedef unsigned long long ull;

__device__ __forceinline__ uint32_t smem_u32(const void* p) {
    uint32_t a;
    asm("{ .reg .u64 t; cvta.to.shared.u64 t, %1; cvt.u32.u64 %0, t; }" : "=r"(a) : "l"(p));
    return a;
}
__device__ __forceinline__ ull pk2(float w){ ull r; asm("mov.b64 %0,{%1,%1};":"=l"(r):"f"(w)); return r; }
__device__ __forceinline__ ull pkf(float a,float b){ ull r; asm("mov.b64 %0,{%1,%2};":"=l"(r):"f"(a),"f"(b)); return r; }
__device__ __forceinline__ void fma2(ull&d,ull a,ull b){ asm("fma.rn.f32x2 %0,%1,%2,%0;":"+l"(d):"l"(a),"l"(b)); }
__device__ __forceinline__ float2 up2(ull v){ float2 f; asm("mov.b64 {%0,%1},%2;":"=f"(f.x),"=f"(f.y):"l"(v)); return f; }
__device__ __forceinline__ float silu_f(float v){ return v/(1.0f+__expf(-v)); }

__host__ __device__ __forceinline__ uint32_t aoff(int r,int k){ return (uint32_t)((r*PDK+k)*2); }

__device__ __forceinline__ void split2(float x,float y,uint32_t&hw,uint32_t&lw){
    __nv_bfloat16 hx=__float2bfloat16_rn(x), hy=__float2bfloat16_rn(y);
    __nv_bfloat16 lx=__float2bfloat16_rn(x-__bfloat162float(hx));
    __nv_bfloat16 ly=__float2bfloat16_rn(y-__bfloat162float(hy));
    hw=(uint32_t)*(uint16_t*)&hx | ((uint32_t)*(uint16_t*)&hy<<16);
    lw=(uint32_t)*(uint16_t*)&lx | ((uint32_t)*(uint16_t*)&ly<<16);
}

__device__ __forceinline__ void ldsm4(uint32_t* r, uint32_t a){
    asm volatile("ldmatrix.sync.aligned.m8n8.x4.shared.b16 {%0,%1,%2,%3}, [%4];"
        : "=r"(r[0]),"=r"(r[1]),"=r"(r[2]),"=r"(r[3]) : "r"(a));
}
__device__ __forceinline__ void ldsm2(uint32_t* r, uint32_t a){
    asm volatile("ldmatrix.sync.aligned.m8n8.x2.shared.b16 {%0,%1}, [%2];"
        : "=r"(r[0]),"=r"(r[1]) : "r"(a));
}
__device__ __forceinline__ void mma_bf16(float* c, const uint32_t* a, const uint32_t* b){
    asm volatile("mma.sync.aligned.m16n8k16.row.col.f32.bf16.bf16.f32 "
        "{%0,%1,%2,%3}, {%4,%5,%6,%7}, {%8,%9}, {%0,%1,%2,%3};"
        : "+f"(c[0]),"+f"(c[1]),"+f"(c[2]),"+f"(c[3])
        : "r"(a[0]),"r"(a[1]),"r"(a[2]),"r"(a[3]),"r"(b[0]),"r"(b[1]));
}

// prepared weight tiles: B[n][k] = W[k][n], bf16 hi/lo, stride PDK
__device__ __align__(16) uint8_t g_w[3][2][TILEB];

__global__ void prep_kernel(const float* __restrict__ We1, const float* __restrict__ We2,
                            const float* __restrict__ Wc1){
    int i = blockIdx.x*blockDim.x + threadIdx.x;
    if(i >= 3*16384) return;
    int m=i>>14, e=i&16383, n=e>>7, k=e&127;
    float v = (m==0) ? We1[(128+k)*HH+n] : (m==1 ? We2[k*HH+n] : Wc1[k*HH+n]);
    __nv_bfloat16 a=__float2bfloat16_rn(v);
    __nv_bfloat16 l=__float2bfloat16_rn(v-__bfloat162float(a));
    uint32_t o=aoff(n,k);
    *(__nv_bfloat16*)(g_w[m][0]+o)=a;
    *(__nv_bfloat16*)(g_w[m][1]+o)=l;
}

__device__ __forceinline__ void copyB(char* sa, int l, int t){
    const uint4* sh=(const uint4*)g_w[l][0]; const uint4* sl=(const uint4*)g_w[l][1];
    uint4* dh=(uint4*)(sa+S_BH); uint4* dl=(uint4*)(sa+S_BL);
    for(int i=t;i<TILEB/16;i+=NTH){ dh[i]=sh[i]; dl[i]=sl[i]; }
}

// 128x128x128 GEMM, 3-pass bf16 split. Warp covers rows R..R+31, cols Cb..Cb+63.
__device__ __forceinline__ void gemm128(uint32_t smb, int R, int Cb, int lane,
                                        float (&acc)[2][8][4]){
#pragma unroll
    for(int mt=0;mt<2;++mt)
#pragma unroll
        for(int nt=0;nt<8;++nt)
#pragma unroll
            for(int i=0;i<4;++i) acc[mt][nt][i]=0.f;

    const uint32_t arow = R + (lane&15);
    const uint32_t acol = 8*(lane>>4);
    const uint32_t brow = Cb + (lane&7);
    const uint32_t bcol = 8*((lane>>3)&1);
    uint32_t aAh = smb + S_AH + aoff(arow, acol);
    uint32_t aAl = smb + S_AL + aoff(arow, acol);
    uint32_t aB  = aoff(brow, bcol);

#pragma unroll 1
    for(int kt=0;kt<8;++kt){
        uint32_t ah0[4],ah1[4],al0[4],al1[4];
        ldsm4(ah0, aAh);            ldsm4(ah1, aAh + aoff(16,0));
        ldsm4(al0, aAl);            ldsm4(al1, aAl + aoff(16,0));
#pragma unroll
        for(int nt=0;nt<8;++nt){
            uint32_t bh[2], bl[2];
            uint32_t bo = aB + (uint32_t)(nt*8*PDK*2) + (uint32_t)(kt*32);
            ldsm2(bh, smb + S_BH + bo);
            ldsm2(bl, smb + S_BL + bo);
            mma_bf16(acc[0][nt], ah0, bh);
            mma_bf16(acc[0][nt], ah0, bl);
            mma_bf16(acc[0][nt], al0, bh);
            mma_bf16(acc[1][nt], ah1, bh);
            mma_bf16(acc[1][nt], ah1, bl);
            mma_bf16(acc[1][nt], al1, bh);
        }
        aAh += 32; aAl += 32;       // K0 += 16 bf16
    }
}

__global__ void __launch_bounds__(NTH,1)
egnn_mma(const float* __restrict__ h, const float* __restrict__ x,
         const int* __restrict__ eidx,
         const float* __restrict__ We1, const float* __restrict__ be1,
         const float* __restrict__ We2, const float* __restrict__ be2,
         const float* __restrict__ Wc1, const float* __restrict__ bc1,
         const float* __restrict__ Wc2,
         const float* __restrict__ Wn1, const float* __restrict__ bn1,
         const float* __restrict__ Wn2, const float* __restrict__ bn2,
         float* __restrict__ out){
    extern __shared__ char sa[];
    const uint32_t smb = smem_u32(sa);
    const int t=threadIdx.x, lane=t&31, wid=t>>5;
    const int mh=wid&3, nh=wid>>2, R=32*mh, Cb=64*nh;
    const int grp=lane>>2, tig=lane&3;
    const int g=blockIdx.x, b=g>>11, n0=(g&2047)*NPB;
    const long bb=(long)b*NN;

    // ---- stage ----
    if(t<128){
        ((int*)(sa+S_IDX))[t]   = eidx[(bb+n0+(t>>4))*KK + (t&15)];
        ((float*)(sa+S_BE1))[t] = be1[t];
        ((float*)(sa+S_WSQ))[t] = We1[256*HH+t];
        ((float*)(sa+S_BE2))[t] = be2[t];
        ((float*)(sa+S_BC1))[t] = bc1[t];
        ((float*)(sa+S_WC2))[t] = Wc2[t];
    }
    if(t<NPB*3) ((float*)(sa+S_XI))[(t/3)*4+t%3] = x[(bb+n0+t/3)*3 + t%3];
    {
        int nd=t>>5, c4=(t&31)*4;
        *(float4*)((float*)(sa+S_HI)+nd*HH+c4) = *(const float4*)(h+(bb+n0+nd)*HH+c4);
    }
    copyB(sa, 0, t);
    __syncthreads();

    // ---- s_i = h_i @ We1[0:128] (FFMA2, warp=node) ----
    {
        int nd=wid, tc=lane*4;
        const float* hi=(float*)(sa+S_HI)+nd*HH;
        ull a01=0,a23=0;
#pragma unroll 4
        for(int i=0;i<HH;++i){
            float4 w=*(const float4*)(We1+i*HH+tc);
            ull hp=pk2(hi[i]);
            fma2(a01,hp,pkf(w.x,w.y)); fma2(a23,hp,pkf(w.z,w.w));
        }
        float2 u=up2(a01), v=up2(a23);
        *(float4*)((float*)(sa+S_SI)+nd*HH+tc)=make_float4(u.x,u.y,v.x,v.y);
    }

    // ---- gather h_neigh -> A tiles (hi/lo), xd/sqd (2 threads per edge) ----
    {
        int e=t>>1, hf=t&1;
        int j=((int*)(sa+S_IDX))[e];
        if(hf==0){
            const float* xi=(float*)(sa+S_XI)+(e>>4)*4;
            const float* xj=x+(bb+j)*3;
            float dx=xi[0]-xj[0], dy=xi[1]-xj[1], dz=xi[2]-xj[2];
            float* xd=(float*)(sa+S_XD)+e*3; xd[0]=dx; xd[1]=dy; xd[2]=dz;
            ((float*)(sa+S_SQD))[e]=dx*dx+dy*dy+dz*dz;
        }
        const float* hj = h + (bb+j)*HH + 64*hf;
#pragma unroll
        for(int q=0;q<8;++q){
            float4 v0=*(const float4*)(hj+q*8), v1=*(const float4*)(hj+q*8+4);
            uint32_t hw[4], lw[4];
            split2(v0.x,v0.y,hw[0],lw[0]); split2(v0.z,v0.w,hw[1],lw[1]);
            split2(v1.x,v1.y,hw[2],lw[2]); split2(v1.z,v1.w,hw[3],lw[3]);
            uint32_t o=aoff(e, 64*hf+q*8);
            *(uint4*)(sa+S_AH+o)=make_uint4(hw[0],hw[1],hw[2],hw[3]);
            *(uint4*)(sa+S_AL+o)=make_uint4(lw[0],lw[1],lw[2],lw[3]);
        }
    }
    __syncthreads();

    float acc[2][8][4];

    // ================= GEMM1 + epi1 =================
    gemm128(smb, R, Cb, lane, acc);
    {
        const float* si=(float*)(sa+S_SI); const float* be1s=(float*)(sa+S_BE1);
        const float* wsqs=(float*)(sa+S_WSQ); const float* sqds=(float*)(sa+S_SQD);
#pragma unroll
        for(int mt=0;mt<2;++mt){
            int nd=2*mh+mt, r0=R+16*mt+grp, r1=r0+8;
            float q0=sqds[r0], q1=sqds[r1];
#pragma unroll
            for(int nt=0;nt<8;++nt){
                int c0=Cb+8*nt+2*tig;
                float s0=si[nd*HH+c0], s1=si[nd*HH+c0+1];
                float b0=be1s[c0], b1=be1s[c0+1];
                float w0=wsqs[c0], w1=wsqs[c0+1];
                float* a=acc[mt][nt];
                a[0]=silu_f(a[0]+s0+b0+q0*w0); a[1]=silu_f(a[1]+s1+b1+q0*w1);
                a[2]=silu_f(a[2]+s0+b0+q1*w0); a[3]=silu_f(a[3]+s1+b1+q1*w1);
            }
        }
    }
    __syncthreads();
#pragma unroll
    for(int mt=0;mt<2;++mt){
        int r0=R+16*mt+grp, r1=r0+8;
#pragma unroll
        for(int nt=0;nt<8;++nt){
            int c0=Cb+8*nt+2*tig; uint32_t hw,lw;
            split2(acc[mt][nt][0],acc[mt][nt][1],hw,lw);
            *(uint32_t*)(sa+S_AH+aoff(r0,c0))=hw; *(uint32_t*)(sa+S_AL+aoff(r0,c0))=lw;
            split2(acc[mt][nt][2],acc[mt][nt][3],hw,lw);
            *(uint32_t*)(sa+S_AH+aoff(r1,c0))=hw; *(uint32_t*)(sa+S_AL+aoff(r1,c0))=lw;
        }
    }
    copyB(sa, 1, t);
    __syncthreads();

    // ================= GEMM2 + epi2 (m_ij, m_i) =================
    gemm128(smb, R, Cb, lane, acc);
    {
        const float* be2s=(float*)(sa+S_BE2);
        float* mi=(float*)(sa+S_MI);
#pragma unroll
        for(int mt=0;mt<2;++mt){
            int nd=2*mh+mt;
#pragma unroll
            for(int nt=0;nt<8;++nt){
                int c0=Cb+8*nt+2*tig;
                float* a=acc[mt][nt];
                a[0]=silu_f(a[0]+be2s[c0]);   a[1]=silu_f(a[1]+be2s[c0+1]);
                a[2]=silu_f(a[2]+be2s[c0]);   a[3]=silu_f(a[3]+be2s[c0+1]);
                float p0=a[0]+a[2], p1=a[1]+a[3];
#pragma unroll
                for(int off=16;off>=4;off>>=1){
                    p0+=__shfl_xor_sync(0xffffffffu,p0,off);
                    p1+=__shfl_xor_sync(0xffffffffu,p1,off);
                }
                if(lane<4){ mi[nd*HH+c0]=p0; mi[nd*HH+c0+1]=p1; }
            }
        }
    }
    __syncthreads();
#pragma unroll
    for(int mt=0;mt<2;++mt){
        int r0=R+16*mt+grp, r1=r0+8;
#pragma unroll
        for(int nt=0;nt<8;++nt){
            int c0=Cb+8*nt+2*tig; uint32_t hw,lw;
            split2(acc[mt][nt][0],acc[mt][nt][1],hw,lw);
            *(uint32_t*)(sa+S_AH+aoff(r0,c0))=hw; *(uint32_t*)(sa+S_AL+aoff(r0,c0))=lw;
            split2(acc[mt][nt][2],acc[mt][nt][3],hw,lw);
            *(uint32_t*)(sa+S_AH+aoff(r1,c0))=hw; *(uint32_t*)(sa+S_AL+aoff(r1,c0))=lw;
        }
    }
    copyB(sa, 2, t);
    __syncthreads();

    // ================= GEMM3 + epi3 (coord weights) =================
    gemm128(smb, R, Cb, lane, acc);
    {
        const float* bc1s=(float*)(sa+S_BC1); const float* wc2s=(float*)(sa+S_WC2);
        float rs[2][2]={{0.f,0.f},{0.f,0.f}};
#pragma unroll
        for(int mt=0;mt<2;++mt)
#pragma unroll
            for(int nt=0;nt<8;++nt){
                int c0=Cb+8*nt+2*tig;
                float* a=acc[mt][nt];
                float v0=silu_f(a[0]+bc1s[c0])*wc2s[c0];
                float v1=silu_f(a[1]+bc1s[c0+1])*wc2s[c0+1];
                float v2=silu_f(a[2]+bc1s[c0])*wc2s[c0];
                float v3=silu_f(a[3]+bc1s[c0+1])*wc2s[c0+1];
                rs[mt][0]+=v0+v1; rs[mt][1]+=v2+v3;
            }
#pragma unroll
        for(int off=1;off<=2;off<<=1)
#pragma unroll
            for(int mt=0;mt<2;++mt){
                rs[mt][0]+=__shfl_xor_sync(0xffffffffu,rs[mt][0],off);
                rs[mt][1]+=__shfl_xor_sync(0xffffffffu,rs[mt][1],off);
            }
        if(tig==0){
            float* cwp=(float*)(sa+S_CWP);
            cwp[(R+grp)*2+nh]=rs[0][0];    cwp[(R+8+grp)*2+nh]=rs[0][1];
            cwp[(R+16+grp)*2+nh]=rs[1][0]; cwp[(R+24+grp)*2+nh]=rs[1][1];
        }
    }
    __syncthreads();

    // ---- x_new ----
    if(t<NPB*3){
        int nd=t/3, d=t%3;
        const float* cwp=(float*)(sa+S_CWP);
        const float* xd=(float*)(sa+S_XD);
        float s=0.f;
#pragma unroll
        for(int k=0;k<KK;++k){
            int e=nd*16+k;
            s += (cwp[e*2]+cwp[e*2+1]) * xd[e*3+d];
        }
        out[(long)NB_*NN*HH + (bb+n0+nd)*3 + d] =
            ((float*)(sa+S_XI))[nd*4+d] + s*(1.f/16.f);
    }

    // ---- node MLP (warp = node, FFMA2) ----
    {
        int nd=wid, tc=lane*4;
        const float* hi=(float*)(sa+S_HI)+nd*HH;
        const float* mi=(float*)(sa+S_MI)+nd*HH;
        ull a01=0,a23=0;
#pragma unroll 2
        for(int i=0;i<HH;++i){
            float4 w1=*(const float4*)(Wn1+i*HH+tc);
            float4 w2=*(const float4*)(Wn1+(128+i)*HH+tc);
            ull hp=pk2(hi[i]), mp=pk2(mi[i]);
            fma2(a01,hp,pkf(w1.x,w1.y)); fma2(a23,hp,pkf(w1.z,w1.w));
            fma2(a01,mp,pkf(w2.x,w2.y)); fma2(a23,mp,pkf(w2.z,w2.w));
        }
        float4 bv=*(const float4*)(bn1+tc);
        float2 u=up2(a01), v=up2(a23);
        *(float4*)((float*)(sa+S_N1)+nd*HH+tc)=
            make_float4(silu_f(u.x+bv.x),silu_f(u.y+bv.y),
                        silu_f(v.x+bv.z),silu_f(v.y+bv.w));
        __syncwarp();
        const float* n1=(float*)(sa+S_N1)+nd*HH;
        ull c01=0,c23=0;
#pragma unroll 4
        for(int i=0;i<HH;++i){
            float4 w=*(const float4*)(Wn2+i*HH+tc);
            ull np=pk2(n1[i]);
            fma2(c01,np,pkf(w.x,w.y)); fma2(c23,np,pkf(w.z,w.w));
        }
        float4 b2=*(const float4*)(bn2+tc);
        float2 p=up2(c01), q=up2(c23);
        *(float4*)(out+(bb+n0+nd)*HH+tc)=
            make_float4(p.x+b2.x+hi[tc], p.y+b2.y+hi[tc+1],
                        q.x+b2.z+hi[tc+2], q.y+b2.w+hi[tc+3]);
    }
}

extern "C" void kernel_launch(void* const* d_in, const int* in_sizes, int n_in,
                              void* d_out, int out_size){
    const float* h   = (const float*)d_in[0];
    const float* x   = (const float*)d_in[1];
    const int*   ei  = (const int*)d_in[2];
    const float* We1 = (const float*)d_in[3];
    const float* be1 = (const float*)d_in[4];
    const float* We2 = (const float*)d_in[5];
    const float* be2 = (const float*)d_in[6];
    const float* Wc1 = (const float*)d_in[7];
    const float* bc1 = (const float*)d_in[8];
    const float* Wc2 = (const float*)d_in[9];
    const float* Wn1 = (const float*)d_in[10];
    const float* bn1 = (const float*)d_in[11];
    const float* Wn2 = (const float*)d_in[12];
    const float* bn2 = (const float*)d_in[13];
    float* out = (float*)d_out;

    prep_kernel<<<192, 256>>>(We1, We2, Wc1);

    cudaFuncSetAttribute(egnn_mma, cudaFuncAttributeMaxDynamicSharedMemorySize, SMEM_TOTAL);
    dim3 grid(NB_*NN/NPB);   // 4096 blocks
    egnn_mma<<<grid, NTH, SMEM_TOTAL>>>(h, x, ei, We1, be1, We2, be2,
                                        Wc1, bc1, Wc2, Wn1, bn1, Wn2, bn2, out);
}

// round 16
// speedup vs baseline: 1.1550x; 1.1550x over previous
#include <cuda_runtime.h>
#include <cuda_bf16.h>
#include <stdint.h>

#define HH 128
#define NB_ 2
#define NN 16384
#define KK 16
#define NPB 8
#define NTH 512
#define PDK 136                      // bf16 row stride (272B, 16B-aligned, conflict-free)
#define TILEB (128 * PDK * 2)        // 34816 bytes per tile

// smem byte offsets
#define S_AH 0
#define S_AL 34816
#define S_BH 69632
#define S_BL 104448
#define S_HI 139264                  // float[8][128]
#define S_SI 143360                  // float[8][128]
#define S_MI 147456                  // float[8][128]
#define S_N1 151552                  // float[8][128]
#define S_BE1 155648
#define S_WSQ 156160
#define S_BE2 156672
#define S_BC1 157184
#define S_WC2 157696
#define S_SQD 158208                 // float[128]
#define S_XD  158720                 // float[128*3]
#define S_XI  160256                 // float[8*4]
#define S_CWP 160384                 // float[128*4]
#define S_IDX 162432                 // int[128]
#define SMEM_TOTAL 162944

typedef unsigned long long ull;

__device__ __forceinline__ uint32_t smem_u32(const void* p) {
    uint32_t a;
    asm("{ .reg .u64 t; cvta.to.shared.u64 t, %1; cvt.u32.u64 %0, t; }" : "=r"(a) : "l"(p));
    return a;
}
__device__ __forceinline__ ull pk2(float w){ ull r; asm("mov.b64 %0,{%1,%1};":"=l"(r):"f"(w)); return r; }
__device__ __forceinline__ ull pkf(float a,float b){ ull r; asm("mov.b64 %0,{%1,%2};":"=l"(r):"f"(a),"f"(b)); return r; }
__device__ __forceinline__ void fma2(ull&d,ull a,ull b){ asm("fma.rn.f32x2 %0,%1,%2,%0;":"+l"(d):"l"(a),"l"(b)); }
__device__ __forceinline__ float2 up2(ull v){ float2 f; asm("mov.b64 {%0,%1},%2;":"=f"(f.x),"=f"(f.y):"l"(v)); return f; }
__device__ __forceinline__ float silu_f(float v){ return v/(1.0f+__expf(-v)); }

__host__ __device__ __forceinline__ uint32_t aoff(int r,int k){ return (uint32_t)((r*PDK+k)*2); }

__device__ __forceinline__ void split2(float x,float y,uint32_t&hw,uint32_t&lw){
    __nv_bfloat16 hx=__float2bfloat16_rn(x), hy=__float2bfloat16_rn(y);
    __nv_bfloat16 lx=__float2bfloat16_rn(x-__bfloat162float(hx));
    __nv_bfloat16 ly=__float2bfloat16_rn(y-__bfloat162float(hy));
    hw=(uint32_t)*(uint16_t*)&hx | ((uint32_t)*(uint16_t*)&hy<<16);
    lw=(uint32_t)*(uint16_t*)&lx | ((uint32_t)*(uint16_t*)&ly<<16);
}

__device__ __forceinline__ void ldsm4(uint32_t* r, uint32_t a){
    asm volatile("ldmatrix.sync.aligned.m8n8.x4.shared.b16 {%0,%1,%2,%3}, [%4];"
        : "=r"(r[0]),"=r"(r[1]),"=r"(r[2]),"=r"(r[3]) : "r"(a));
}
__device__ __forceinline__ void ldsm2(uint32_t* r, uint32_t a){
    asm volatile("ldmatrix.sync.aligned.m8n8.x2.shared.b16 {%0,%1}, [%2];"
        : "=r"(r[0]),"=r"(r[1]) : "r"(a));
}
__device__ __forceinline__ void mma_bf16(float* c, const uint32_t* a, const uint32_t* b){
    asm volatile("mma.sync.aligned.m16n8k16.row.col.f32.bf16.bf16.f32 "
        "{%0,%1,%2,%3}, {%4,%5,%6,%7}, {%8,%9}, {%0,%1,%2,%3};"
        : "+f"(c[0]),"+f"(c[1]),"+f"(c[2]),"+f"(c[3])
        : "r"(a[0]),"r"(a[1]),"r"(a[2]),"r"(a[3]),"r"(b[0]),"r"(b[1]));
}

// prepared weight tiles: B[n][k] = W[k][n], bf16 hi/lo, stride PDK
__device__ __align__(16) uint8_t g_w[3][2][TILEB];

__global__ void prep_kernel(const float* __restrict__ We1, const float* __restrict__ We2,
                            const float* __restrict__ Wc1){
    int i = blockIdx.x*blockDim.x + threadIdx.x;
    if(i >= 3*16384) return;
    int m=i>>14, e=i&16383, n=e>>7, k=e&127;
    float v = (m==0) ? We1[(128+k)*HH+n] : (m==1 ? We2[k*HH+n] : Wc1[k*HH+n]);
    __nv_bfloat16 a=__float2bfloat16_rn(v);
    __nv_bfloat16 l=__float2bfloat16_rn(v-__bfloat162float(a));
    uint32_t o=aoff(n,k);
    *(__nv_bfloat16*)(g_w[m][0]+o)=a;
    *(__nv_bfloat16*)(g_w[m][1]+o)=l;
}

__device__ __forceinline__ void copyB(char* sa, int l, int t){
    const uint4* sh=(const uint4*)g_w[l][0]; const uint4* sl=(const uint4*)g_w[l][1];
    uint4* dh=(uint4*)(sa+S_BH); uint4* dl=(uint4*)(sa+S_BL);
    for(int i=t;i<TILEB/16;i+=NTH){ dh[i]=sh[i]; dl[i]=sl[i]; }
}

// 128x128x128 GEMM, 3-pass bf16 split. Warp covers rows R..R+31, cols Cb..Cb+31.
__device__ __forceinline__ void gemm128(uint32_t smb, int R, int Cb, int lane,
                                        float (&acc)[2][4][4]){
#pragma unroll
    for(int mt=0;mt<2;++mt)
#pragma unroll
        for(int nt=0;nt<4;++nt)
#pragma unroll
            for(int i=0;i<4;++i) acc[mt][nt][i]=0.f;

    const uint32_t arow = R + (lane&15);
    const uint32_t acol = 8*(lane>>4);
    const uint32_t brow = Cb + (lane&7);
    const uint32_t bcol = 8*((lane>>3)&1);
    uint32_t aAh = smb + S_AH + aoff(arow, acol);
    uint32_t aAl = smb + S_AL + aoff(arow, acol);
    uint32_t aB  = aoff(brow, bcol);

#pragma unroll 1
    for(int kt=0;kt<8;++kt){
        uint32_t ah0[4],ah1[4],al0[4],al1[4];
        ldsm4(ah0, aAh);            ldsm4(ah1, aAh + aoff(16,0));
        ldsm4(al0, aAl);            ldsm4(al1, aAl + aoff(16,0));
#pragma unroll
        for(int nt=0;nt<4;++nt){
            uint32_t bh[2], bl[2];
            uint32_t bo = aB + (uint32_t)(nt*8*PDK*2) + (uint32_t)(kt*32);
            ldsm2(bh, smb + S_BH + bo);
            ldsm2(bl, smb + S_BL + bo);
            mma_bf16(acc[0][nt], ah0, bh);
            mma_bf16(acc[0][nt], ah0, bl);
            mma_bf16(acc[0][nt], al0, bh);
            mma_bf16(acc[1][nt], ah1, bh);
            mma_bf16(acc[1][nt], ah1, bl);
            mma_bf16(acc[1][nt], al1, bh);
        }
        aAh += 32; aAl += 32;       // K0 += 16 bf16
    }
}

__global__ void __launch_bounds__(NTH,1)
egnn_mma(const float* __restrict__ h, const float* __restrict__ x,
         const int* __restrict__ eidx,
         const float* __restrict__ We1, const float* __restrict__ be1,
         const float* __restrict__ We2, const float* __restrict__ be2,
         const float* __restrict__ Wc1, const float* __restrict__ bc1,
         const float* __restrict__ Wc2,
         const float* __restrict__ Wn1, const float* __restrict__ bn1,
         const float* __restrict__ Wn2, const float* __restrict__ bn2,
         float* __restrict__ out){
    extern __shared__ char sa[];
    const uint32_t smb = smem_u32(sa);
    const int t=threadIdx.x, lane=t&31, wid=t>>5;          // 16 warps
    const int mh=wid&3, nh=wid>>2, R=32*mh, Cb=32*nh;      // warp tile 32x32
    const int grp=lane>>2, tig=lane&3;
    const int g=blockIdx.x, b=g>>11, n0=(g&2047)*NPB;
    const long bb=(long)b*NN;

    // ---- stage ----
    if(t<128){
        ((int*)(sa+S_IDX))[t]   = eidx[(bb+n0+(t>>4))*KK + (t&15)];
        ((float*)(sa+S_BE1))[t] = be1[t];
        ((float*)(sa+S_WSQ))[t] = We1[256*HH+t];
        ((float*)(sa+S_BE2))[t] = be2[t];
        ((float*)(sa+S_BC1))[t] = bc1[t];
        ((float*)(sa+S_WC2))[t] = Wc2[t];
    }
    if(t<NPB*3) ((float*)(sa+S_XI))[(t/3)*4+t%3] = x[(bb+n0+t/3)*3 + t%3];
    if(t<256){
        int nd=t>>5, c4=(t&31)*4;
        *(float4*)((float*)(sa+S_HI)+nd*HH+c4) = *(const float4*)(h+(bb+n0+nd)*HH+c4);
    }
    copyB(sa, 0, t);
    __syncthreads();

    // ---- s_i = h_i @ We1[0:128] (FFMA2, warp-pair = node, 2 cols/thread) ----
    {
        int nd=wid>>1, c=(wid&1)*64 + lane*2;
        const float* hi=(float*)(sa+S_HI)+nd*HH;
        ull a01=0;
#pragma unroll 4
        for(int i=0;i<HH;++i)
            fma2(a01, pk2(hi[i]), pkf(We1[i*HH+c], We1[i*HH+c+1]));
        float2 u=up2(a01);
        *(float2*)((float*)(sa+S_SI)+nd*HH+c)=u;
    }

    // ---- gather h_neigh -> A tiles (hi/lo), xd/sqd (4 threads per edge) ----
    {
        int e=t>>2, part=t&3;
        int j=((int*)(sa+S_IDX))[e];
        if(part==0){
            const float* xi=(float*)(sa+S_XI)+(e>>4)*4;
            const float* xj=x+(bb+j)*3;
            float dx=xi[0]-xj[0], dy=xi[1]-xj[1], dz=xi[2]-xj[2];
            float* xd=(float*)(sa+S_XD)+e*3; xd[0]=dx; xd[1]=dy; xd[2]=dz;
            ((float*)(sa+S_SQD))[e]=dx*dx+dy*dy+dz*dz;
        }
        const float* hj = h + (bb+j)*HH + 32*part;
#pragma unroll
        for(int q=0;q<4;++q){
            float4 v0=*(const float4*)(hj+q*8), v1=*(const float4*)(hj+q*8+4);
            uint32_t hw[4], lw[4];
            split2(v0.x,v0.y,hw[0],lw[0]); split2(v0.z,v0.w,hw[1],lw[1]);
            split2(v1.x,v1.y,hw[2],lw[2]); split2(v1.z,v1.w,hw[3],lw[3]);
            uint32_t o=aoff(e, 32*part+q*8);
            *(uint4*)(sa+S_AH+o)=make_uint4(hw[0],hw[1],hw[2],hw[3]);
            *(uint4*)(sa+S_AL+o)=make_uint4(lw[0],lw[1],lw[2],lw[3]);
        }
    }
    __syncthreads();

    float acc[2][4][4];

    // ================= GEMM1 + epi1 =================
    gemm128(smb, R, Cb, lane, acc);
    {
        const float* si=(float*)(sa+S_SI); const float* be1s=(float*)(sa+S_BE1);
        const float* wsqs=(float*)(sa+S_WSQ); const float* sqds=(float*)(sa+S_SQD);
#pragma unroll
        for(int mt=0;mt<2;++mt){
            int nd=2*mh+mt, r0=R+16*mt+grp, r1=r0+8;
            float q0=sqds[r0], q1=sqds[r1];
#pragma unroll
            for(int nt=0;nt<4;++nt){
                int c0=Cb+8*nt+2*tig;
                float s0=si[nd*HH+c0], s1=si[nd*HH+c0+1];
                float b0=be1s[c0], b1=be1s[c0+1];
                float w0=wsqs[c0], w1=wsqs[c0+1];
                float* a=acc[mt][nt];
                a[0]=silu_f(a[0]+s0+b0+q0*w0); a[1]=silu_f(a[1]+s1+b1+q0*w1);
                a[2]=silu_f(a[2]+s0+b0+q1*w0); a[3]=silu_f(a[3]+s1+b1+q1*w1);
            }
        }
    }
    __syncthreads();
#pragma unroll
    for(int mt=0;mt<2;++mt){
        int r0=R+16*mt+grp, r1=r0+8;
#pragma unroll
        for(int nt=0;nt<4;++nt){
            int c0=Cb+8*nt+2*tig; uint32_t hw,lw;
            split2(acc[mt][nt][0],acc[mt][nt][1],hw,lw);
            *(uint32_t*)(sa+S_AH+aoff(r0,c0))=hw; *(uint32_t*)(sa+S_AL+aoff(r0,c0))=lw;
            split2(acc[mt][nt][2],acc[mt][nt][3],hw,lw);
            *(uint32_t*)(sa+S_AH+aoff(r1,c0))=hw; *(uint32_t*)(sa+S_AL+aoff(r1,c0))=lw;
        }
    }
    copyB(sa, 1, t);
    __syncthreads();

    // ================= GEMM2 + epi2 (m_ij, m_i) =================
    gemm128(smb, R, Cb, lane, acc);
    {
        const float* be2s=(float*)(sa+S_BE2);
        float* mi=(float*)(sa+S_MI);
#pragma unroll
        for(int mt=0;mt<2;++mt){
            int nd=2*mh+mt;
#pragma unroll
            for(int nt=0;nt<4;++nt){
                int c0=Cb+8*nt+2*tig;
                float* a=acc[mt][nt];
                a[0]=silu_f(a[0]+be2s[c0]);   a[1]=silu_f(a[1]+be2s[c0+1]);
                a[2]=silu_f(a[2]+be2s[c0]);   a[3]=silu_f(a[3]+be2s[c0+1]);
                float p0=a[0]+a[2], p1=a[1]+a[3];
#pragma unroll
                for(int off=16;off>=4;off>>=1){
                    p0+=__shfl_xor_sync(0xffffffffu,p0,off);
                    p1+=__shfl_xor_sync(0xffffffffu,p1,off);
                }
                if(lane<4){ mi[nd*HH+c0]=p0; mi[nd*HH+c0+1]=p1; }
            }
        }
    }
    __syncthreads();
#pragma unroll
    for(int mt=0;mt<2;++mt){
        int r0=R+16*mt+grp, r1=r0+8;
#pragma unroll
        for(int nt=0;nt<4;++nt){
            int c0=Cb+8*nt+2*tig; uint32_t hw,lw;
            split2(acc[mt][nt][0],acc[mt][nt][1],hw,lw);
            *(uint32_t*)(sa+S_AH+aoff(r0,c0))=hw; *(uint32_t*)(sa+S_AL+aoff(r0,c0))=lw;
            split2(acc[mt][nt][2],acc[mt][nt][3],hw,lw);
            *(uint32_t*)(sa+S_AH+aoff(r1,c0))=hw; *(uint32_t*)(sa+S_AL+aoff(r1,c0))=lw;
        }
    }
    copyB(sa, 2, t);
    __syncthreads();

    // ================= GEMM3 + epi3 (coord weights) =================
    gemm128(smb, R, Cb, lane, acc);
    {
        const float* bc1s=(float*)(sa+S_BC1); const float* wc2s=(float*)(sa+S_WC2);
        float rs[2][2]={{0.f,0.f},{0.f,0.f}};
#pragma unroll
        for(int mt=0;mt<2;++mt)
#pragma unroll
            for(int nt=0;nt<4;++nt){
                int c0=Cb+8*nt+2*tig;
                float* a=acc[mt][nt];
                float v0=silu_f(a[0]+bc1s[c0])*wc2s[c0];
                float v1=silu_f(a[1]+bc1s[c0+1])*wc2s[c0+1];
                float v2=silu_f(a[2]+bc1s[c0])*wc2s[c0];
                float v3=silu_f(a[3]+bc1s[c0+1])*wc2s[c0+1];
                rs[mt][0]+=v0+v1; rs[mt][1]+=v2+v3;
            }
        // reduce across tig (cols within warp quarter-lanes)
#pragma unroll
        for(int off=1;off<=2;off<<=1)
#pragma unroll
            for(int mt=0;mt<2;++mt){
                rs[mt][0]+=__shfl_xor_sync(0xffffffffu,rs[mt][0],off);
                rs[mt][1]+=__shfl_xor_sync(0xffffffffu,rs[mt][1],off);
            }
        if(tig==0){
            float* cwp=(float*)(sa+S_CWP);
            cwp[(R+grp)*4+nh]=rs[0][0];    cwp[(R+8+grp)*4+nh]=rs[0][1];
            cwp[(R+16+grp)*4+nh]=rs[1][0]; cwp[(R+24+grp)*4+nh]=rs[1][1];
        }
    }
    __syncthreads();

    // ---- x_new ----
    if(t<NPB*3){
        int nd=t/3, d=t%3;
        const float* cwp=(float*)(sa+S_CWP);
        const float* xd=(float*)(sa+S_XD);
        float s=0.f;
#pragma unroll
        for(int k=0;k<KK;++k){
            int e=nd*16+k;
            s += (cwp[e*4]+cwp[e*4+1]+cwp[e*4+2]+cwp[e*4+3]) * xd[e*3+d];
        }
        out[(long)NB_*NN*HH + (bb+n0+nd)*3 + d] =
            ((float*)(sa+S_XI))[nd*4+d] + s*(1.f/16.f);
    }

    // ---- node MLP (warp-pair = node, 2 cols/thread, FFMA2) ----
    {
        int nd=wid>>1, c=(wid&1)*64 + lane*2;
        const float* hi=(float*)(sa+S_HI)+nd*HH;
        const float* mi=(float*)(sa+S_MI)+nd*HH;
        ull a01=0;
#pragma unroll 2
        for(int i=0;i<HH;++i){
            fma2(a01, pk2(hi[i]), pkf(Wn1[i*HH+c], Wn1[i*HH+c+1]));
            fma2(a01, pk2(mi[i]), pkf(Wn1[(128+i)*HH+c], Wn1[(128+i)*HH+c+1]));
        }
        float2 u=up2(a01);
        ((float*)(sa+S_N1))[nd*HH+c]   = silu_f(u.x+bn1[c]);
        ((float*)(sa+S_N1))[nd*HH+c+1] = silu_f(u.y+bn1[c+1]);
    }
    __syncthreads();
    {
        int nd=wid>>1, c=(wid&1)*64 + lane*2;
        const float* n1=(float*)(sa+S_N1)+nd*HH;
        const float* hi=(float*)(sa+S_HI)+nd*HH;
        ull c01=0;
#pragma unroll 4
        for(int i=0;i<HH;++i)
            fma2(c01, pk2(n1[i]), pkf(Wn2[i*HH+c], Wn2[i*HH+c+1]));
        float2 p=up2(c01);
        float2 res = make_float2(p.x+bn2[c]+hi[c], p.y+bn2[c+1]+hi[c+1]);
        *(float2*)(out+(bb+n0+nd)*HH+c)=res;
    }
}

extern "C" void kernel_launch(void* const* d_in, const int* in_sizes, int n_in,
                              void* d_out, int out_size){
    const float* h   = (const float*)d_in[0];
    const float* x   = (const float*)d_in[1];
    const int*   ei  = (const int*)d_in[2];
    const float* We1 = (const float*)d_in[3];
    const float* be1 = (const float*)d_in[4];
    const float* We2 = (const float*)d_in[5];
    const float* be2 = (const float*)d_in[6];
    const float* Wc1 = (const float*)d_in[7];
    const float* bc1 = (const float*)d_in[8];
    const float* Wc2 = (const float*)d_in[9];
    const float* Wn1 = (const float*)d_in[10];
    const float* bn1 = (const float*)d_in[11];
    const float* Wn2 = (const float*)d_in[12];
    const float* bn2 = (const float*)d_in[13];
    float* out = (float*)d_out;

    prep_kernel<<<192, 256>>>(We1, We2, Wc1);

    cudaFuncSetAttribute(egnn_mma, cudaFuncAttributeMaxDynamicSharedMemorySize, SMEM_TOTAL);
    dim3 grid(NB_*NN/NPB);   // 4096 blocks
    egnn_mma<<<grid, NTH, SMEM_TOTAL>>>(h, x, ei, We1, be1, We2, be2,
                                        Wc1, bc1, Wc2, Wn1, bn1, Wn2, bn2, out);
}